// round 2
// baseline (speedup 1.0000x reference)
#include <cuda_runtime.h>
#include <cstdint>
#include <cstdio>

// ---------------------------------------------------------------------------
// MultiSAGE fused pipeline.
//
//   agg_t[d] += feat[s]  (t=0,1,2)   cnt_t[d]++            (edge scatter, RED.v4)
//   mean_t = agg_t / max(cnt_t,1)    mean_all = (Σagg)/max(Σcnt,1)
//   X  = [mean0|mean1|mean2|mean_all|feat]                 (N x 640)
//   comb = relu(X @ W_big + b_big)   (W_big folds wt[] into Wl*/Wr*/Wla/Wra)
//   BN: column sums/sumsq -> a[j], c[j]  (affine, applied explicitly in X2)
//   agg_c[d] += comb[s] over union edges (cnt reused)
//   X2 = [a*(agg_c/cnt_all) + c*1{cnt>0} | a*comb + c]
//   out = X2 @ [Wf^T; Wrf^T] + bf
// ---------------------------------------------------------------------------

#define DIM 128
constexpr int MAXN = 100000;
constexpr int PADN = MAXN + 128;   // pad so GEMM row-tiles never index OOB

__device__ __align__(16) float d_agg[3][(size_t)PADN * DIM];
__device__ int   d_cnt[3][PADN];
__device__ int   d_cntall[PADN];
__device__ float d_r[4][PADN];
__device__ __align__(16) float d_X[(size_t)PADN * 640];
__device__ __align__(16) float d_comb[(size_t)PADN * DIM];
__device__ __align__(16) float d_aggc[(size_t)PADN * DIM];
__device__ __align__(16) float d_X2[(size_t)PADN * 256];
__device__ __align__(16) float d_Wbig[640 * DIM];
__device__ float d_bcomb[DIM];
__device__ __align__(16) float d_W2p[256 * DIM];
__device__ float d_b2[DIM];
__device__ float d_colsum[DIM];
__device__ float d_colsumsq[DIM];
__device__ __align__(16) float d_bn_a[DIM];
__device__ __align__(16) float d_bn_c[DIM];

// ---------------------------------------------------------------------------
// helpers
// ---------------------------------------------------------------------------
__device__ __forceinline__ unsigned long long dup_f32(float x) {
    unsigned long long r;
    unsigned int u = __float_as_uint(x);
    asm("mov.b64 %0, {%1, %1};" : "=l"(r) : "r"(u));
    return r;
}
__device__ __forceinline__ void fma_f32x2(unsigned long long& d,
                                          unsigned long long a,
                                          unsigned long long b) {
    asm("fma.rn.f32x2 %0, %1, %2, %0;" : "+l"(d) : "l"(a), "l"(b));
}
__device__ __forceinline__ void red_add_v4(float* p, float4 v) {
    asm volatile("red.global.add.v4.f32 [%0], {%1, %2, %3, %4};"
                 :: "l"(p), "f"(v.x), "f"(v.y), "f"(v.z), "f"(v.w) : "memory");
}

// ---------------------------------------------------------------------------
// zero scratch that is accumulated into
// ---------------------------------------------------------------------------
__global__ void zero_kernel(int n) {
    size_t i = (size_t)blockIdx.x * blockDim.x + threadIdx.x;
    size_t stride = (size_t)gridDim.x * blockDim.x;
    size_t n4 = (size_t)n * (DIM / 4);
    float4 z = make_float4(0.f, 0.f, 0.f, 0.f);
    for (size_t k = i; k < n4; k += stride) {
        ((float4*)d_agg[0])[k] = z;
        ((float4*)d_agg[1])[k] = z;
        ((float4*)d_agg[2])[k] = z;
        ((float4*)d_aggc)[k]   = z;
    }
    for (size_t k = i; k < (size_t)n; k += stride) {
        d_cnt[0][k] = 0; d_cnt[1][k] = 0; d_cnt[2][k] = 0;
    }
    if (i < DIM) { d_colsum[i] = 0.f; d_colsumsq[i] = 0.f; }
}

// ---------------------------------------------------------------------------
// weight prep 1: W_big[640][128], b_big[128]
// ---------------------------------------------------------------------------
__global__ void prep1_kernel(const float* __restrict__ Wl0, const float* __restrict__ Wl1,
                             const float* __restrict__ Wl2, const float* __restrict__ Wla,
                             const float* __restrict__ Wr0, const float* __restrict__ Wr1,
                             const float* __restrict__ Wr2, const float* __restrict__ Wra,
                             const float* __restrict__ bl0, const float* __restrict__ bl1,
                             const float* __restrict__ bl2, const float* __restrict__ bla,
                             const float* __restrict__ wt) {
    int idx = blockIdx.x * blockDim.x + threadIdx.x;
    float w0 = wt[0], w1 = wt[1], w2 = wt[2];
    if (idx < 640 * DIM) {
        int j = idx & (DIM - 1);
        int k = idx >> 7;
        int reg = k >> 7;
        int km = k & (DIM - 1);
        int wij = j * DIM + km;   // W[j][km] : W^T layout for the GEMM
        float v;
        switch (reg) {
            case 0:  v = w0 * Wl0[wij]; break;
            case 1:  v = w1 * Wl1[wij]; break;
            case 2:  v = w2 * Wl2[wij]; break;
            case 3:  v = Wla[wij]; break;
            default: v = w0 * Wr0[wij] + w1 * Wr1[wij] + w2 * Wr2[wij] + Wra[wij];
        }
        d_Wbig[idx] = v;
    } else if (idx < 640 * DIM + DIM) {
        int j = idx - 640 * DIM;
        d_bcomb[j] = w0 * bl0[j] + w1 * bl1[j] + w2 * bl2[j] + bla[j];
    }
}

// ---------------------------------------------------------------------------
// edge scatter: one warp per edge, 16B vector reductions
// ---------------------------------------------------------------------------
__global__ void scatter_feat_kernel(const float* __restrict__ feat,
                                    const int* __restrict__ e, int E, int t) {
    int gw = (blockIdx.x * blockDim.x + threadIdx.x) >> 5;
    int lane = threadIdx.x & 31;
    if (gw >= E) return;
    int s = __ldg(e + gw);
    int d = __ldg(e + E + gw);
    float4 v = *(const float4*)(feat + (size_t)s * DIM + lane * 4);
    red_add_v4(&d_agg[t][(size_t)d * DIM + lane * 4], v);
    if (lane == 0) atomicAdd(&d_cnt[t][d], 1);
}

__global__ void scatter_comb_kernel(const int* __restrict__ e, int E) {
    int gw = (blockIdx.x * blockDim.x + threadIdx.x) >> 5;
    int lane = threadIdx.x & 31;
    if (gw >= E) return;
    int s = __ldg(e + gw);
    int d = __ldg(e + E + gw);
    float4 v = *(const float4*)(d_comb + (size_t)s * DIM + lane * 4);
    red_add_v4(&d_aggc[(size_t)d * DIM + lane * 4], v);
}

// ---------------------------------------------------------------------------
// reciprocal counts
// ---------------------------------------------------------------------------
__global__ void build_r_kernel(int n) {
    int i = blockIdx.x * blockDim.x + threadIdx.x;
    if (i >= n) return;
    int c0 = d_cnt[0][i], c1 = d_cnt[1][i], c2 = d_cnt[2][i];
    d_r[0][i] = 1.f / (float)(c0 > 1 ? c0 : 1);
    d_r[1][i] = 1.f / (float)(c1 > 1 ? c1 : 1);
    d_r[2][i] = 1.f / (float)(c2 > 1 ? c2 : 1);
    int ca = c0 + c1 + c2;
    d_cntall[i] = ca;
    d_r[3][i] = 1.f / (float)(ca > 1 ? ca : 1);
}

// ---------------------------------------------------------------------------
// X = [mean0|mean1|mean2|mean_all|feat]   (N x 640), float4 elementwise
// ---------------------------------------------------------------------------
__global__ void build_X_kernel(const float* __restrict__ feat, int n) {
    size_t i = (size_t)blockIdx.x * blockDim.x + threadIdx.x;
    size_t stride = (size_t)gridDim.x * blockDim.x;
    size_t total = (size_t)n * 160;   // float4s per row = 640/4
    for (size_t idx = i; idx < total; idx += stride) {
        size_t ni = idx / 160;
        int rem = (int)(idx - ni * 160);
        int reg = rem >> 5;           // 0..4 (32 float4 per 128-block)
        int w = rem & 31;
        size_t base = ni * 32 + w;
        float4 v;
        if (reg < 3) {
            v = ((const float4*)d_agg[reg])[base];
            float s = d_r[reg][ni];
            v.x *= s; v.y *= s; v.z *= s; v.w *= s;
        } else if (reg == 3) {
            float4 v0 = ((const float4*)d_agg[0])[base];
            float4 v1 = ((const float4*)d_agg[1])[base];
            float4 v2 = ((const float4*)d_agg[2])[base];
            float s = d_r[3][ni];
            v.x = (v0.x + v1.x + v2.x) * s;
            v.y = (v0.y + v1.y + v2.y) * s;
            v.z = (v0.z + v1.z + v2.z) * s;
            v.w = (v0.w + v1.w + v2.w) * s;
        } else {
            v = ((const float4*)feat)[base];
        }
        ((float4*)d_X)[idx] = v;
    }
}

// X2 = [ a*(agg_c/cnt_all) + c*1{cnt_all>0}  |  a*comb + c ]   (N x 256)
// BN applied explicitly here; the zero-in-degree indicator is load-bearing:
// mean_agg(BN(comb)) has NO constant term for nodes with no union in-edges.
__global__ void build_X2_kernel(int n) {
    size_t i = (size_t)blockIdx.x * blockDim.x + threadIdx.x;
    size_t stride = (size_t)gridDim.x * blockDim.x;
    size_t total = (size_t)n * 64;
    for (size_t idx = i; idx < total; idx += stride) {
        size_t ni = idx >> 6;
        int rem = (int)(idx & 63);
        int reg = rem >> 5;
        int w = rem & 31;
        size_t base = ni * 32 + w;
        float4 a4 = ((const float4*)d_bn_a)[w];
        float4 c4 = ((const float4*)d_bn_c)[w];
        float4 v, o;
        if (reg == 0) {
            v = ((const float4*)d_aggc)[base];
            float s = d_r[3][ni];
            float has = (d_cntall[ni] > 0) ? 1.f : 0.f;
            o.x = fmaf(a4.x, v.x * s, c4.x * has);
            o.y = fmaf(a4.y, v.y * s, c4.y * has);
            o.z = fmaf(a4.z, v.z * s, c4.z * has);
            o.w = fmaf(a4.w, v.w * s, c4.w * has);
        } else {
            v = ((const float4*)d_comb)[base];
            o.x = fmaf(a4.x, v.x, c4.x);
            o.y = fmaf(a4.y, v.y, c4.y);
            o.z = fmaf(a4.z, v.z, c4.z);
            o.w = fmaf(a4.w, v.w, c4.w);
        }
        ((float4*)d_X2)[idx] = o;
    }
}

// ---------------------------------------------------------------------------
// BN column stats
// ---------------------------------------------------------------------------
__global__ void bn_stats_kernel(int n) {
    int j = threadIdx.x;
    float s = 0.f, s2 = 0.f;
    for (int r = blockIdx.x; r < n; r += gridDim.x) {
        float v = d_comb[(size_t)r * DIM + j];
        s += v;
        s2 += v * v;
    }
    atomicAdd(&d_colsum[j], s);
    atomicAdd(&d_colsumsq[j], s2);
}

// ---------------------------------------------------------------------------
// weight prep 2: plain [Wf^T; Wrf^T], b2 = bf, plus BN affine coefs a/c
// ---------------------------------------------------------------------------
__global__ void prep2_kernel(const float* __restrict__ Wf, const float* __restrict__ Wrf,
                             const float* __restrict__ bf, const float* __restrict__ gamma,
                             const float* __restrict__ beta, int n) {
    int b = blockIdx.x;
    int j = threadIdx.x;
    if (b < 256) {
        int km = b & (DIM - 1);
        const float* Wsrc = (b < DIM) ? Wf : Wrf;
        d_W2p[b * DIM + j] = Wsrc[j * DIM + km];
    } else {
        float invn = 1.f / (float)n;
        float mu = d_colsum[j] * invn;
        float var = d_colsumsq[j] * invn - mu * mu;
        float a = gamma[j] * rsqrtf(var + 1e-5f);
        d_bn_a[j] = a;
        d_bn_c[j] = beta[j] - mu * a;
        d_b2[j] = bf[j];
    }
}

// ---------------------------------------------------------------------------
// SGEMM: C[n x 128] = A[n x K] @ W[K x 128] + bias, optional relu.
// 128x128 block tile, 8x8 per-thread micro tile, fma.rn.f32x2 inner loop.
// ---------------------------------------------------------------------------
template <bool RELU>
__global__ __launch_bounds__(256, 2)
void gemm_bias_kernel(const float* __restrict__ A, const float* __restrict__ W,
                      const float* __restrict__ bias, float* __restrict__ C,
                      int nrows, int K) {
    __shared__ float As[16][128];   // [k][m] transposed
    __shared__ float Bs[16][128];   // [k][j]

    const int tid = threadIdx.x;
    const int m0 = blockIdx.x * 128;
    const int ty = tid >> 4;           // 0..15 -> row group of 8
    const int tx = tid & 15;           // 0..15 -> col group of 8
    const int ar = tid >> 1;           // A-load row 0..127
    const int ak = (tid & 1) * 8;      // A-load k offset
    const int kb = tid >> 4;           // B-load k row 0..15
    const int cb = (tid & 15) * 8;     // B-load col
    const bool arow_ok = (m0 + ar) < nrows;
    const float* Ap = A + (size_t)(m0 + ar) * K + ak;
    const float* Wp = W + (size_t)kb * 128 + cb;

    unsigned long long acc[4][8];   // acc[i2][j] packs rows (2*i2, 2*i2+1), col j
#pragma unroll
    for (int i = 0; i < 4; i++)
#pragma unroll
        for (int j = 0; j < 8; j++) acc[i][j] = 0ull;

    for (int k0 = 0; k0 < K; k0 += 16) {
        float4 a0 = make_float4(0.f, 0.f, 0.f, 0.f), a1 = a0;
        if (arow_ok) {
            a0 = *(const float4*)(Ap + k0);
            a1 = *(const float4*)(Ap + k0 + 4);
        }
        float4 b0 = *(const float4*)(Wp + (size_t)k0 * 128);
        float4 b1 = *(const float4*)(Wp + (size_t)k0 * 128 + 4);
        __syncthreads();
        As[ak + 0][ar] = a0.x; As[ak + 1][ar] = a0.y;
        As[ak + 2][ar] = a0.z; As[ak + 3][ar] = a0.w;
        As[ak + 4][ar] = a1.x; As[ak + 5][ar] = a1.y;
        As[ak + 6][ar] = a1.z; As[ak + 7][ar] = a1.w;
        *(float4*)&Bs[kb][cb] = b0;
        *(float4*)&Bs[kb][cb + 4] = b1;
        __syncthreads();
#pragma unroll
        for (int kk = 0; kk < 16; kk++) {
            const unsigned long long* ap =
                (const unsigned long long*)&As[kk][ty * 8];
            unsigned long long a2_0 = ap[0], a2_1 = ap[1], a2_2 = ap[2], a2_3 = ap[3];
            const float* bp = &Bs[kk][tx * 8];
            float4 f0 = *(const float4*)bp;
            float4 f1 = *(const float4*)(bp + 4);
            unsigned long long bd[8];
            bd[0] = dup_f32(f0.x); bd[1] = dup_f32(f0.y);
            bd[2] = dup_f32(f0.z); bd[3] = dup_f32(f0.w);
            bd[4] = dup_f32(f1.x); bd[5] = dup_f32(f1.y);
            bd[6] = dup_f32(f1.z); bd[7] = dup_f32(f1.w);
#pragma unroll
            for (int j = 0; j < 8; j++) {
                fma_f32x2(acc[0][j], a2_0, bd[j]);
                fma_f32x2(acc[1][j], a2_1, bd[j]);
                fma_f32x2(acc[2][j], a2_2, bd[j]);
                fma_f32x2(acc[3][j], a2_3, bd[j]);
            }
        }
    }

    float bv[8];
#pragma unroll
    for (int j = 0; j < 8; j++) bv[j] = bias[tx * 8 + j];

#pragma unroll
    for (int i2 = 0; i2 < 4; i2++) {
        float lo[8], hi[8];
#pragma unroll
        for (int j = 0; j < 8; j++) {
            lo[j] = __uint_as_float((unsigned)(acc[i2][j] & 0xffffffffull)) + bv[j];
            hi[j] = __uint_as_float((unsigned)(acc[i2][j] >> 32)) + bv[j];
            if (RELU) {
                lo[j] = fmaxf(lo[j], 0.f);
                hi[j] = fmaxf(hi[j], 0.f);
            }
        }
        int rlo = m0 + ty * 8 + i2 * 2;
        if (rlo < nrows) {
            float* p = C + (size_t)rlo * 128 + tx * 8;
            *(float4*)p       = make_float4(lo[0], lo[1], lo[2], lo[3]);
            *(float4*)(p + 4) = make_float4(lo[4], lo[5], lo[6], lo[7]);
        }
        if (rlo + 1 < nrows) {
            float* p = C + (size_t)(rlo + 1) * 128 + tx * 8;
            *(float4*)p       = make_float4(hi[0], hi[1], hi[2], hi[3]);
            *(float4*)(p + 4) = make_float4(hi[4], hi[5], hi[6], hi[7]);
        }
    }
}

// ---------------------------------------------------------------------------
// launch
// ---------------------------------------------------------------------------
extern "C" void kernel_launch(void* const* d_in, const int* in_sizes, int n_in,
                              void* d_out, int out_size) {
    // ---- identify inputs by size (robust to metadata ordering) ----
    int feat_i = 0;
    for (int i = 1; i < n_in; i++)
        if (in_sizes[i] > in_sizes[feat_i]) feat_i = i;

    const float* Wm[10] = {0};
    const float* Bv[7]  = {0};
    const int*   Ee[3]  = {0};
    int Ecnt[3] = {0};
    const float* wt = nullptr;
    int wn = 0, bn = 0, en = 0;
    for (int i = 0; i < n_in; i++) {
        if (i == feat_i) continue;
        int s = in_sizes[i];
        if (s == 3)                wt = (const float*)d_in[i];
        else if (s == DIM)         { if (bn < 7)  Bv[bn++] = (const float*)d_in[i]; }
        else if (s == DIM * DIM)   { if (wn < 10) Wm[wn++] = (const float*)d_in[i]; }
        else                       { if (en < 3)  { Ee[en] = (const int*)d_in[i];
                                                    Ecnt[en] = s / 2; en++; } }
    }
    const float* feat = (const float*)d_in[feat_i];
    int n = in_sizes[feat_i] / DIM;

    // order within each size class follows the reference signature:
    const float *Wl0 = Wm[0], *Wr0 = Wm[1], *Wl1 = Wm[2], *Wr1 = Wm[3];
    const float *Wl2 = Wm[4], *Wr2 = Wm[5], *Wla = Wm[6], *Wra = Wm[7];
    const float *Wf  = Wm[8], *Wrf = Wm[9];
    const float *bl0 = Bv[0], *bl1 = Bv[1], *bl2 = Bv[2], *bla = Bv[3];
    const float *bf  = Bv[4], *gamma = Bv[5], *beta = Bv[6];

    float *pX, *pWbig, *pbcomb, *pcomb, *pX2, *pW2p, *pb2;
    cudaGetSymbolAddress((void**)&pX, d_X);
    cudaGetSymbolAddress((void**)&pWbig, d_Wbig);
    cudaGetSymbolAddress((void**)&pbcomb, d_bcomb);
    cudaGetSymbolAddress((void**)&pcomb, d_comb);
    cudaGetSymbolAddress((void**)&pX2, d_X2);
    cudaGetSymbolAddress((void**)&pW2p, d_W2p);
    cudaGetSymbolAddress((void**)&pb2, d_b2);

    float* out = (float*)d_out;

    zero_kernel<<<2048, 256>>>(n);
    prep1_kernel<<<(640 * DIM + DIM + 255) / 256, 256>>>(
        Wl0, Wl1, Wl2, Wla, Wr0, Wr1, Wr2, Wra, bl0, bl1, bl2, bla, wt);

    for (int t = 0; t < 3; t++)
        scatter_feat_kernel<<<(Ecnt[t] + 7) / 8, 256>>>(feat, Ee[t], Ecnt[t], t);

    build_r_kernel<<<(n + 255) / 256, 256>>>(n);
    build_X_kernel<<<8192, 256>>>(feat, n);

    gemm_bias_kernel<true><<<(n + 127) / 128, 256>>>(pX, pWbig, pbcomb, pcomb, n, 640);

    bn_stats_kernel<<<1024, 128>>>(n);

    for (int t = 0; t < 3; t++)
        scatter_comb_kernel<<<(Ecnt[t] + 7) / 8, 256>>>(Ee[t], Ecnt[t]);

    prep2_kernel<<<257, 128>>>(Wf, Wrf, bf, gamma, beta, n);
    build_X2_kernel<<<4096, 256>>>(n);

    gemm_bias_kernel<false><<<(n + 127) / 128, 256>>>(pX2, pW2p, pb2, out, n, 256);

    (void)out_size;
}

// round 3
// speedup vs baseline: 1.1463x; 1.1463x over previous
#include <cuda_runtime.h>
#include <cstdint>
#include <cstdio>

// ---------------------------------------------------------------------------
// MultiSAGE fused pipeline, v3: zero intermediate materialization.
//
//   scatter:  agg_t[d] += feat[s], cnt_t[d]++   (one merged kernel, RED.v4)
//   GEMM1 reads A-tiles straight from [r0*agg0 | r1*agg1 | r2*agg2 |
//          r3*(agg0+agg1+agg2) | feat] (row scales applied at load),
//          epilogue: +bias, relu, store comb, fused BN column sum/sumsq.
//   bn_finalize: a = gamma*rsqrt(var+eps), c = beta - mu*a
//   scatter2: aggc[d] += comb[s] over union edges (one merged kernel)
//   GEMM2 reads [r3*aggc | comb], W2p = diag(a)-folded [Wf^T;Wrf^T],
//          epilogue: + bf + c@Wrf^T + has[row]*(c@Wf^T)
// ---------------------------------------------------------------------------

#define DIM 128
constexpr int MAXN = 100000;
constexpr int PADN = MAXN + 128;

__device__ __align__(16) float d_agg[3][(size_t)PADN * DIM];
__device__ int   d_cnt[3][PADN];
__device__ float d_has[PADN];
__device__ float d_r[4][PADN];
__device__ __align__(16) float d_comb[(size_t)PADN * DIM];
__device__ __align__(16) float d_aggc[(size_t)PADN * DIM];
__device__ __align__(16) float d_Wbig[640 * DIM];
__device__ float d_bcomb[DIM];
__device__ __align__(16) float d_W2p[256 * DIM];
__device__ float d_b2[DIM];     // bf + c @ Wrf^T
__device__ float d_cWf[DIM];    // c @ Wf^T
__device__ float d_colsum[DIM];
__device__ float d_colsumsq[DIM];
__device__ __align__(16) float d_bn_a[DIM];
__device__ __align__(16) float d_bn_c[DIM];

// ---------------------------------------------------------------------------
// helpers
// ---------------------------------------------------------------------------
__device__ __forceinline__ unsigned long long dup_f32(float x) {
    unsigned long long r;
    unsigned int u = __float_as_uint(x);
    asm("mov.b64 %0, {%1, %1};" : "=l"(r) : "r"(u));
    return r;
}
__device__ __forceinline__ void fma_f32x2(unsigned long long& d,
                                          unsigned long long a,
                                          unsigned long long b) {
    asm("fma.rn.f32x2 %0, %1, %2, %0;" : "+l"(d) : "l"(a), "l"(b));
}
__device__ __forceinline__ void red_add_v4(float* p, float4 v) {
    asm volatile("red.global.add.v4.f32 [%0], {%1, %2, %3, %4};"
                 :: "l"(p), "f"(v.x), "f"(v.y), "f"(v.z), "f"(v.w) : "memory");
}

// ---------------------------------------------------------------------------
__global__ void zero_kernel(int n) {
    size_t i = (size_t)blockIdx.x * blockDim.x + threadIdx.x;
    size_t stride = (size_t)gridDim.x * blockDim.x;
    size_t n4 = (size_t)n * (DIM / 4);
    float4 z = make_float4(0.f, 0.f, 0.f, 0.f);
    for (size_t k = i; k < n4; k += stride) {
        ((float4*)d_agg[0])[k] = z;
        ((float4*)d_agg[1])[k] = z;
        ((float4*)d_agg[2])[k] = z;
        ((float4*)d_aggc)[k]   = z;
    }
    for (size_t k = i; k < (size_t)n; k += stride) {
        d_cnt[0][k] = 0; d_cnt[1][k] = 0; d_cnt[2][k] = 0;
    }
    if (i < DIM) { d_colsum[i] = 0.f; d_colsumsq[i] = 0.f; }
}

// ---------------------------------------------------------------------------
// weight prep 1: W_big[640][128] (wt folded), b_big
// ---------------------------------------------------------------------------
__global__ void prep1_kernel(const float* __restrict__ Wl0, const float* __restrict__ Wl1,
                             const float* __restrict__ Wl2, const float* __restrict__ Wla,
                             const float* __restrict__ Wr0, const float* __restrict__ Wr1,
                             const float* __restrict__ Wr2, const float* __restrict__ Wra,
                             const float* __restrict__ bl0, const float* __restrict__ bl1,
                             const float* __restrict__ bl2, const float* __restrict__ bla,
                             const float* __restrict__ wt) {
    int idx = blockIdx.x * blockDim.x + threadIdx.x;
    float w0 = wt[0], w1 = wt[1], w2 = wt[2];
    if (idx < 640 * DIM) {
        int j = idx & (DIM - 1);
        int k = idx >> 7;
        int reg = k >> 7;
        int km = k & (DIM - 1);
        int wij = j * DIM + km;
        float v;
        switch (reg) {
            case 0:  v = w0 * Wl0[wij]; break;
            case 1:  v = w1 * Wl1[wij]; break;
            case 2:  v = w2 * Wl2[wij]; break;
            case 3:  v = Wla[wij]; break;
            default: v = w0 * Wr0[wij] + w1 * Wr1[wij] + w2 * Wr2[wij] + Wra[wij];
        }
        d_Wbig[idx] = v;
    } else if (idx < 640 * DIM + DIM) {
        int j = idx - 640 * DIM;
        d_bcomb[j] = w0 * bl0[j] + w1 * bl1[j] + w2 * bl2[j] + bla[j];
    }
}

// ---------------------------------------------------------------------------
// merged edge scatter over all three edge types (one warp per edge)
// ---------------------------------------------------------------------------
__global__ void scatter_feat_all(const float* __restrict__ feat,
                                 const int* __restrict__ e0, const int* __restrict__ e1,
                                 const int* __restrict__ e2, int E0, int E1, int E2) {
    int gw = (blockIdx.x * blockDim.x + threadIdx.x) >> 5;
    int lane = threadIdx.x & 31;
    const int* e; int t, E, idx = gw;
    if (idx < E0)            { e = e0; t = 0; E = E0; }
    else if ((idx -= E0) < E1) { e = e1; t = 1; E = E1; }
    else if ((idx -= E1) < E2) { e = e2; t = 2; E = E2; }
    else return;
    int s = __ldg(e + idx);
    int d = __ldg(e + E + idx);
    float4 v = *(const float4*)(feat + (size_t)s * DIM + lane * 4);
    red_add_v4(&d_agg[t][(size_t)d * DIM + lane * 4], v);
    if (lane == 0) atomicAdd(&d_cnt[t][d], 1);
}

__global__ void scatter_comb_all(const int* __restrict__ e0, const int* __restrict__ e1,
                                 const int* __restrict__ e2, int E0, int E1, int E2) {
    int gw = (blockIdx.x * blockDim.x + threadIdx.x) >> 5;
    int lane = threadIdx.x & 31;
    const int* e; int E, idx = gw;
    if (idx < E0)            { e = e0; E = E0; }
    else if ((idx -= E0) < E1) { e = e1; E = E1; }
    else if ((idx -= E1) < E2) { e = e2; E = E2; }
    else return;
    int s = __ldg(e + idx);
    int d = __ldg(e + E + idx);
    float4 v = *(const float4*)(d_comb + (size_t)s * DIM + lane * 4);
    red_add_v4(&d_aggc[(size_t)d * DIM + lane * 4], v);
}

// ---------------------------------------------------------------------------
__global__ void build_r_kernel(int n) {
    int i = blockIdx.x * blockDim.x + threadIdx.x;
    if (i >= n) return;
    int c0 = d_cnt[0][i], c1 = d_cnt[1][i], c2 = d_cnt[2][i];
    d_r[0][i] = 1.f / (float)(c0 > 1 ? c0 : 1);
    d_r[1][i] = 1.f / (float)(c1 > 1 ? c1 : 1);
    d_r[2][i] = 1.f / (float)(c2 > 1 ? c2 : 1);
    int ca = c0 + c1 + c2;
    d_has[i] = (ca > 0) ? 1.f : 0.f;
    d_r[3][i] = 1.f / (float)(ca > 1 ? ca : 1);
}

// ---------------------------------------------------------------------------
// GEMM1: comb = relu([r0*agg0|r1*agg1|r2*agg2|r3*sum|feat] @ Wbig + bcomb)
// 128x128 tile, 8x8 micro, fma.rn.f32x2; fused BN column sum/sumsq epilogue.
// ---------------------------------------------------------------------------
__global__ __launch_bounds__(256, 2)
void gemm1_kernel(const float* __restrict__ feat, int nrows) {
    __shared__ float As[16][128];
    __shared__ float Bs[16][128];

    const int tid = threadIdx.x;
    const int m0 = blockIdx.x * 128;
    const int ty = tid >> 4;
    const int tx = tid & 15;
    const int ar = tid >> 1;
    const int ak = (tid & 1) * 8;
    const int kb = tid >> 4;
    const int cb = (tid & 15) * 8;
    const int arow = m0 + ar;
    const bool arow_ok = arow < nrows;
    const float* Wp = d_Wbig + (size_t)kb * 128 + cb;

    float rr0 = 0.f, rr1 = 0.f, rr2 = 0.f, rr3 = 0.f;
    if (arow_ok) {
        rr0 = d_r[0][arow]; rr1 = d_r[1][arow];
        rr2 = d_r[2][arow]; rr3 = d_r[3][arow];
    }
    const size_t rowoff = (size_t)arow * DIM;

    unsigned long long acc[4][8];
#pragma unroll
    for (int i = 0; i < 4; i++)
#pragma unroll
        for (int j = 0; j < 8; j++) acc[i][j] = 0ull;

    for (int k0 = 0; k0 < 640; k0 += 16) {
        int reg = k0 >> 7;
        int lk = (k0 & 127) + ak;
        float4 a0 = make_float4(0.f, 0.f, 0.f, 0.f), a1 = a0;
        if (arow_ok) {
            if (reg < 3) {
                const float* p = d_agg[reg] + rowoff + lk;
                float s = (reg == 0) ? rr0 : (reg == 1 ? rr1 : rr2);
                a0 = *(const float4*)p;
                a1 = *(const float4*)(p + 4);
                a0.x *= s; a0.y *= s; a0.z *= s; a0.w *= s;
                a1.x *= s; a1.y *= s; a1.z *= s; a1.w *= s;
            } else if (reg == 3) {
                const float4* p0 = (const float4*)(d_agg[0] + rowoff + lk);
                const float4* p1 = (const float4*)(d_agg[1] + rowoff + lk);
                const float4* p2 = (const float4*)(d_agg[2] + rowoff + lk);
                float4 u0 = p0[0], u1 = p1[0], u2 = p2[0];
                float4 w0 = p0[1], w1 = p1[1], w2 = p2[1];
                a0.x = (u0.x + u1.x + u2.x) * rr3;
                a0.y = (u0.y + u1.y + u2.y) * rr3;
                a0.z = (u0.z + u1.z + u2.z) * rr3;
                a0.w = (u0.w + u1.w + u2.w) * rr3;
                a1.x = (w0.x + w1.x + w2.x) * rr3;
                a1.y = (w0.y + w1.y + w2.y) * rr3;
                a1.z = (w0.z + w1.z + w2.z) * rr3;
                a1.w = (w0.w + w1.w + w2.w) * rr3;
            } else {
                const float* p = feat + rowoff + lk;
                a0 = *(const float4*)p;
                a1 = *(const float4*)(p + 4);
            }
        }
        float4 b0 = *(const float4*)(Wp + (size_t)k0 * 128);
        float4 b1 = *(const float4*)(Wp + (size_t)k0 * 128 + 4);
        __syncthreads();
        As[ak + 0][ar] = a0.x; As[ak + 1][ar] = a0.y;
        As[ak + 2][ar] = a0.z; As[ak + 3][ar] = a0.w;
        As[ak + 4][ar] = a1.x; As[ak + 5][ar] = a1.y;
        As[ak + 6][ar] = a1.z; As[ak + 7][ar] = a1.w;
        *(float4*)&Bs[kb][cb] = b0;
        *(float4*)&Bs[kb][cb + 4] = b1;
        __syncthreads();
#pragma unroll
        for (int kk = 0; kk < 16; kk++) {
            const unsigned long long* ap =
                (const unsigned long long*)&As[kk][ty * 8];
            unsigned long long a2_0 = ap[0], a2_1 = ap[1], a2_2 = ap[2], a2_3 = ap[3];
            const float* bp = &Bs[kk][tx * 8];
            float4 f0 = *(const float4*)bp;
            float4 f1 = *(const float4*)(bp + 4);
            unsigned long long bd[8];
            bd[0] = dup_f32(f0.x); bd[1] = dup_f32(f0.y);
            bd[2] = dup_f32(f0.z); bd[3] = dup_f32(f0.w);
            bd[4] = dup_f32(f1.x); bd[5] = dup_f32(f1.y);
            bd[6] = dup_f32(f1.z); bd[7] = dup_f32(f1.w);
#pragma unroll
            for (int j = 0; j < 8; j++) {
                fma_f32x2(acc[0][j], a2_0, bd[j]);
                fma_f32x2(acc[1][j], a2_1, bd[j]);
                fma_f32x2(acc[2][j], a2_2, bd[j]);
                fma_f32x2(acc[3][j], a2_3, bd[j]);
            }
        }
    }

    float bv[8];
#pragma unroll
    for (int j = 0; j < 8; j++) bv[j] = d_bcomb[tx * 8 + j];

    float cs[8], cs2[8];
#pragma unroll
    for (int j = 0; j < 8; j++) { cs[j] = 0.f; cs2[j] = 0.f; }

#pragma unroll
    for (int i2 = 0; i2 < 4; i2++) {
        float lo[8], hi[8];
#pragma unroll
        for (int j = 0; j < 8; j++) {
            lo[j] = fmaxf(__uint_as_float((unsigned)(acc[i2][j] & 0xffffffffull)) + bv[j], 0.f);
            hi[j] = fmaxf(__uint_as_float((unsigned)(acc[i2][j] >> 32)) + bv[j], 0.f);
        }
        int rlo = m0 + ty * 8 + i2 * 2;
        if (rlo < nrows) {
            float* p = d_comb + (size_t)rlo * 128 + tx * 8;
            *(float4*)p       = make_float4(lo[0], lo[1], lo[2], lo[3]);
            *(float4*)(p + 4) = make_float4(lo[4], lo[5], lo[6], lo[7]);
#pragma unroll
            for (int j = 0; j < 8; j++) { cs[j] += lo[j]; cs2[j] += lo[j] * lo[j]; }
        }
        if (rlo + 1 < nrows) {
            float* p = d_comb + (size_t)(rlo + 1) * 128 + tx * 8;
            *(float4*)p       = make_float4(hi[0], hi[1], hi[2], hi[3]);
            *(float4*)(p + 4) = make_float4(hi[4], hi[5], hi[6], hi[7]);
#pragma unroll
            for (int j = 0; j < 8; j++) { cs[j] += hi[j]; cs2[j] += hi[j] * hi[j]; }
        }
    }

    // fused BN column-stat reduction: smem (reuse As/Bs), 256 atomics per block
    __syncthreads();
    float* sbuf  = &As[0][0];
    float* s2buf = &Bs[0][0];
#pragma unroll
    for (int j = 0; j < 8; j++) {
        sbuf[tid * 8 + j]  = cs[j];
        s2buf[tid * 8 + j] = cs2[j];
    }
    __syncthreads();
    if (tid < 128) {
        int j = tid, txj = j >> 3, jj = j & 7;
        float ss = 0.f, ss2 = 0.f;
#pragma unroll
        for (int t = 0; t < 16; t++) {
            int src = (t * 16 + txj) * 8 + jj;
            ss  += sbuf[src];
            ss2 += s2buf[src];
        }
        atomicAdd(&d_colsum[j], ss);
        atomicAdd(&d_colsumsq[j], ss2);
    }
}

// ---------------------------------------------------------------------------
__global__ void bn_finalize_kernel(const float* __restrict__ gamma,
                                   const float* __restrict__ beta, int n) {
    int j = threadIdx.x;
    float invn = 1.f / (float)n;
    float mu = d_colsum[j] * invn;
    float var = d_colsumsq[j] * invn - mu * mu;
    float a = gamma[j] * rsqrtf(var + 1e-5f);
    d_bn_a[j] = a;
    d_bn_c[j] = beta[j] - mu * a;
}

// prep2: W2p = diag(a)-folded [Wf^T;Wrf^T]; b2 = bf + c@Wrf^T; cWf = c@Wf^T
__global__ void prep2_kernel(const float* __restrict__ Wf, const float* __restrict__ Wrf,
                             const float* __restrict__ bf) {
    int b = blockIdx.x;
    int j = threadIdx.x;
    if (b < 256) {
        int km = b & (DIM - 1);
        const float* Wsrc = (b < DIM) ? Wf : Wrf;
        d_W2p[b * DIM + j] = d_bn_a[km] * Wsrc[j * DIM + km];
    } else {
        float accf = 0.f, accr = 0.f;
        for (int k = 0; k < DIM; k++) {
            float c = d_bn_c[k];
            accf += c * Wf[j * DIM + k];
            accr += c * Wrf[j * DIM + k];
        }
        d_cWf[j] = accf;
        d_b2[j] = bf[j] + accr;
    }
}

// ---------------------------------------------------------------------------
// GEMM2: out = [r3*aggc | comb] @ W2p + b2 + has[row]*cWf
// ---------------------------------------------------------------------------
__global__ __launch_bounds__(256, 2)
void gemm2_kernel(float* __restrict__ C, int nrows) {
    __shared__ float As[16][128];
    __shared__ float Bs[16][128];

    const int tid = threadIdx.x;
    const int m0 = blockIdx.x * 128;
    const int ty = tid >> 4;
    const int tx = tid & 15;
    const int ar = tid >> 1;
    const int ak = (tid & 1) * 8;
    const int kb = tid >> 4;
    const int cb = (tid & 15) * 8;
    const int arow = m0 + ar;
    const bool arow_ok = arow < nrows;
    const float* Wp = d_W2p + (size_t)kb * 128 + cb;

    float rr3 = arow_ok ? d_r[3][arow] : 0.f;
    const size_t rowoff = (size_t)arow * DIM;

    unsigned long long acc[4][8];
#pragma unroll
    for (int i = 0; i < 4; i++)
#pragma unroll
        for (int j = 0; j < 8; j++) acc[i][j] = 0ull;

    for (int k0 = 0; k0 < 256; k0 += 16) {
        int reg = k0 >> 7;
        int lk = (k0 & 127) + ak;
        float4 a0 = make_float4(0.f, 0.f, 0.f, 0.f), a1 = a0;
        if (arow_ok) {
            if (reg == 0) {
                const float* p = d_aggc + rowoff + lk;
                a0 = *(const float4*)p;
                a1 = *(const float4*)(p + 4);
                a0.x *= rr3; a0.y *= rr3; a0.z *= rr3; a0.w *= rr3;
                a1.x *= rr3; a1.y *= rr3; a1.z *= rr3; a1.w *= rr3;
            } else {
                const float* p = d_comb + rowoff + lk;
                a0 = *(const float4*)p;
                a1 = *(const float4*)(p + 4);
            }
        }
        float4 b0 = *(const float4*)(Wp + (size_t)k0 * 128);
        float4 b1 = *(const float4*)(Wp + (size_t)k0 * 128 + 4);
        __syncthreads();
        As[ak + 0][ar] = a0.x; As[ak + 1][ar] = a0.y;
        As[ak + 2][ar] = a0.z; As[ak + 3][ar] = a0.w;
        As[ak + 4][ar] = a1.x; As[ak + 5][ar] = a1.y;
        As[ak + 6][ar] = a1.z; As[ak + 7][ar] = a1.w;
        *(float4*)&Bs[kb][cb] = b0;
        *(float4*)&Bs[kb][cb + 4] = b1;
        __syncthreads();
#pragma unroll
        for (int kk = 0; kk < 16; kk++) {
            const unsigned long long* ap =
                (const unsigned long long*)&As[kk][ty * 8];
            unsigned long long a2_0 = ap[0], a2_1 = ap[1], a2_2 = ap[2], a2_3 = ap[3];
            const float* bp = &Bs[kk][tx * 8];
            float4 f0 = *(const float4*)bp;
            float4 f1 = *(const float4*)(bp + 4);
            unsigned long long bd[8];
            bd[0] = dup_f32(f0.x); bd[1] = dup_f32(f0.y);
            bd[2] = dup_f32(f0.z); bd[3] = dup_f32(f0.w);
            bd[4] = dup_f32(f1.x); bd[5] = dup_f32(f1.y);
            bd[6] = dup_f32(f1.z); bd[7] = dup_f32(f1.w);
#pragma unroll
            for (int j = 0; j < 8; j++) {
                fma_f32x2(acc[0][j], a2_0, bd[j]);
                fma_f32x2(acc[1][j], a2_1, bd[j]);
                fma_f32x2(acc[2][j], a2_2, bd[j]);
                fma_f32x2(acc[3][j], a2_3, bd[j]);
            }
        }
    }

    float bv[8], cw[8];
#pragma unroll
    for (int j = 0; j < 8; j++) {
        bv[j] = d_b2[tx * 8 + j];
        cw[j] = d_cWf[tx * 8 + j];
    }

#pragma unroll
    for (int i2 = 0; i2 < 4; i2++) {
        int rlo = m0 + ty * 8 + i2 * 2;
        if (rlo < nrows) {
            float h = d_has[rlo];
            float lo[8];
#pragma unroll
            for (int j = 0; j < 8; j++)
                lo[j] = __uint_as_float((unsigned)(acc[i2][j] & 0xffffffffull))
                        + bv[j] + h * cw[j];
            float* p = C + (size_t)rlo * 128 + tx * 8;
            *(float4*)p       = make_float4(lo[0], lo[1], lo[2], lo[3]);
            *(float4*)(p + 4) = make_float4(lo[4], lo[5], lo[6], lo[7]);
        }
        if (rlo + 1 < nrows) {
            float h = d_has[rlo + 1];
            float hi[8];
#pragma unroll
            for (int j = 0; j < 8; j++)
                hi[j] = __uint_as_float((unsigned)(acc[i2][j] >> 32))
                        + bv[j] + h * cw[j];
            float* p = C + (size_t)(rlo + 1) * 128 + tx * 8;
            *(float4*)p       = make_float4(hi[0], hi[1], hi[2], hi[3]);
            *(float4*)(p + 4) = make_float4(hi[4], hi[5], hi[6], hi[7]);
        }
    }
}

// ---------------------------------------------------------------------------
// launch
// ---------------------------------------------------------------------------
extern "C" void kernel_launch(void* const* d_in, const int* in_sizes, int n_in,
                              void* d_out, int out_size) {
    int feat_i = 0;
    for (int i = 1; i < n_in; i++)
        if (in_sizes[i] > in_sizes[feat_i]) feat_i = i;

    const float* Wm[10] = {0};
    const float* Bv[7]  = {0};
    const int*   Ee[3]  = {0};
    int Ecnt[3] = {0};
    const float* wt = nullptr;
    int wn = 0, bn = 0, en = 0;
    for (int i = 0; i < n_in; i++) {
        if (i == feat_i) continue;
        int s = in_sizes[i];
        if (s == 3)                wt = (const float*)d_in[i];
        else if (s == DIM)         { if (bn < 7)  Bv[bn++] = (const float*)d_in[i]; }
        else if (s == DIM * DIM)   { if (wn < 10) Wm[wn++] = (const float*)d_in[i]; }
        else                       { if (en < 3)  { Ee[en] = (const int*)d_in[i];
                                                    Ecnt[en] = s / 2; en++; } }
    }
    const float* feat = (const float*)d_in[feat_i];
    int n = in_sizes[feat_i] / DIM;

    const float *Wl0 = Wm[0], *Wr0 = Wm[1], *Wl1 = Wm[2], *Wr1 = Wm[3];
    const float *Wl2 = Wm[4], *Wr2 = Wm[5], *Wla = Wm[6], *Wra = Wm[7];
    const float *Wf  = Wm[8], *Wrf = Wm[9];
    const float *bl0 = Bv[0], *bl1 = Bv[1], *bl2 = Bv[2], *bla = Bv[3];
    const float *bf  = Bv[4], *gamma = Bv[5], *beta = Bv[6];

    float* out = (float*)d_out;
    int Etot = Ecnt[0] + Ecnt[1] + Ecnt[2];
    int nblk = (n + 127) / 128;

    zero_kernel<<<2048, 256>>>(n);
    prep1_kernel<<<(640 * DIM + DIM + 255) / 256, 256>>>(
        Wl0, Wl1, Wl2, Wla, Wr0, Wr1, Wr2, Wra, bl0, bl1, bl2, bla, wt);

    scatter_feat_all<<<(Etot + 7) / 8, 256>>>(feat, Ee[0], Ee[1], Ee[2],
                                              Ecnt[0], Ecnt[1], Ecnt[2]);
    build_r_kernel<<<(n + 255) / 256, 256>>>(n);

    gemm1_kernel<<<nblk, 256>>>(feat, n);

    bn_finalize_kernel<<<1, 128>>>(gamma, beta, n);

    scatter_comb_all<<<(Etot + 7) / 8, 256>>>(Ee[0], Ee[1], Ee[2],
                                              Ecnt[0], Ecnt[1], Ecnt[2]);
    prep2_kernel<<<257, 128>>>(Wf, Wrf, bf);

    gemm2_kernel<<<nblk, 256>>>(out, n);

    (void)out_size;
}

// round 8
// speedup vs baseline: 1.6349x; 1.4262x over previous
#include <cuda_runtime.h>
#include <cuda_bf16.h>
#include <cstdint>
#include <cstdio>

// ---------------------------------------------------------------------------
// MultiSAGE fused pipeline, v6: mma.sync (m16n8k16 bf16, fp32 accum) GEMMs
// with bf16 hi/lo 3-pass fp32 emulation. tcgen05 is NOT available through
// this harness (PTX stage targets compute_103 without the 'a' suffix), so
// everything here is arch-portable PTX: mma.sync + ldmatrix.
//
//   scatter:  agg_t[d] += feat[s], cnt_t[d]++
//   GEMM1:   comb = relu([r0*agg0|r1*agg1|r2*agg2|r3*sum|feat] @ Wbig + b)
//   bn_stats -> bn_finalize: a, c
//   scatter2: aggc[d] += comb[s]
//   GEMM2:   out = [r3*aggc | comb] @ diag(a)[Wf^T;Wrf^T] + bf + cWrf + has*cWf
// ---------------------------------------------------------------------------

#define DIM 128
constexpr int MAXN = 100000;
constexpr int PADN = MAXN + 128;

__device__ __align__(16) float d_agg[3][(size_t)PADN * DIM];
__device__ int   d_cnt[3][PADN];
__device__ float d_has[PADN];
__device__ float d_r[4][PADN];
__device__ __align__(16) float d_comb[(size_t)PADN * DIM];
__device__ __align__(16) float d_aggc[(size_t)PADN * DIM];
// bf16 hi/lo weight operands, [j][k] K-major (row j = output col)
__device__ __align__(16) __nv_bfloat16 d_B1hi[128 * 640];
__device__ __align__(16) __nv_bfloat16 d_B1lo[128 * 640];
__device__ __align__(16) __nv_bfloat16 d_B2hi[128 * 256];
__device__ __align__(16) __nv_bfloat16 d_B2lo[128 * 256];
__device__ float d_bcomb[DIM];
__device__ float d_b2[DIM];
__device__ float d_cWf[DIM];
__device__ float d_colsum[DIM];
__device__ float d_colsumsq[DIM];
__device__ __align__(16) float d_bn_a[DIM];
__device__ __align__(16) float d_bn_c[DIM];

// ---------------------------------------------------------------------------
// helpers
// ---------------------------------------------------------------------------
__device__ __forceinline__ uint32_t smem_u32(const void* p) {
    uint32_t a;
    asm("{ .reg .u64 t; cvta.to.shared.u64 t, %1; cvt.u32.u64 %0, t; }"
        : "=r"(a) : "l"(p));
    return a;
}
__device__ __forceinline__ void red_add_v4(float* p, float4 v) {
    asm volatile("red.global.add.v4.f32 [%0], {%1, %2, %3, %4};"
                 :: "l"(p), "f"(v.x), "f"(v.y), "f"(v.z), "f"(v.w) : "memory");
}
__device__ __forceinline__ void ldmx4(uint32_t* r, uint32_t addr) {
    asm volatile("ldmatrix.sync.aligned.m8n8.x4.shared.b16 {%0,%1,%2,%3}, [%4];"
                 : "=r"(r[0]), "=r"(r[1]), "=r"(r[2]), "=r"(r[3]) : "r"(addr));
}
// D = A*B + D, bf16 inputs, f32 accum. Fragment layouts (PTX ISA):
//  a0=(row g, k 2t..+1) a1=(g+8,k) a2=(g,k+8) a3=(g+8,k+8)  [g=lane>>2, t=lane&3]
//  b0=(k 2t..+1, n g)   b1=(k+8, n g)
//  c0=(g, 2t) c1=(g, 2t+1) c2=(g+8, 2t) c3=(g+8, 2t+1)
__device__ __forceinline__ void mma_bf16(float* d, const uint32_t* a,
                                         uint32_t b0, uint32_t b1) {
    asm volatile(
        "mma.sync.aligned.m16n8k16.row.col.f32.bf16.bf16.f32 "
        "{%0,%1,%2,%3}, {%4,%5,%6,%7}, {%8,%9}, {%0,%1,%2,%3};"
        : "+f"(d[0]), "+f"(d[1]), "+f"(d[2]), "+f"(d[3])
        : "r"(a[0]), "r"(a[1]), "r"(a[2]), "r"(a[3]), "r"(b0), "r"(b1));
}

__device__ __forceinline__ uint32_t pack_bf2(float a, float b) {
    __nv_bfloat162 t;
    t.x = __float2bfloat16(a);
    t.y = __float2bfloat16(b);
    return *reinterpret_cast<uint32_t*>(&t);
}
__device__ __forceinline__ float bf_round(float a) {
    return __bfloat162float(__float2bfloat16(a));
}

// Tile geometry: 128 rows x 32 bf16 per smem tile, row stride 80 B
// (64 B payload + 16 B pad -> ldmatrix phase conflict-free).
constexpr int TROW = 80;

// store 16 fp32 (4 float4, already scaled) as 16 hi + 16 lo bf16 at row,khalf
__device__ __forceinline__ void store16(char* hi, char* lo, int off,
                                        float4 f0, float4 f1, float4 f2, float4 f3) {
    uint4 H0, H1, L0, L1;
    H0.x = pack_bf2(f0.x, f0.y); H0.y = pack_bf2(f0.z, f0.w);
    H0.z = pack_bf2(f1.x, f1.y); H0.w = pack_bf2(f1.z, f1.w);
    H1.x = pack_bf2(f2.x, f2.y); H1.y = pack_bf2(f2.z, f2.w);
    H1.z = pack_bf2(f3.x, f3.y); H1.w = pack_bf2(f3.z, f3.w);
    L0.x = pack_bf2(f0.x - bf_round(f0.x), f0.y - bf_round(f0.y));
    L0.y = pack_bf2(f0.z - bf_round(f0.z), f0.w - bf_round(f0.w));
    L0.z = pack_bf2(f1.x - bf_round(f1.x), f1.y - bf_round(f1.y));
    L0.w = pack_bf2(f1.z - bf_round(f1.z), f1.w - bf_round(f1.w));
    L1.x = pack_bf2(f2.x - bf_round(f2.x), f2.y - bf_round(f2.y));
    L1.y = pack_bf2(f2.z - bf_round(f2.z), f2.w - bf_round(f2.w));
    L1.z = pack_bf2(f3.x - bf_round(f3.x), f3.y - bf_round(f3.y));
    L1.w = pack_bf2(f3.z - bf_round(f3.z), f3.w - bf_round(f3.w));
    *(uint4*)(hi + off)      = H0;
    *(uint4*)(hi + off + 16) = H1;
    *(uint4*)(lo + off)      = L0;
    *(uint4*)(lo + off + 16) = L1;
}

// B tile fill: thread t covers row t>>1 (=output col j), k-half (t&1)*16
__device__ __forceinline__ void fill_b(const __nv_bfloat16* __restrict__ Bh,
                                       const __nv_bfloat16* __restrict__ Bl,
                                       int Ktot, int c0, int tid,
                                       char* sBhi, char* sBlo) {
    int row = tid >> 1, kh = (tid & 1) * 16;
    const uint4* ph = (const uint4*)(Bh + (size_t)row * Ktot + c0 + kh);
    const uint4* pl = (const uint4*)(Bl + (size_t)row * Ktot + c0 + kh);
    uint4 h0 = ph[0], h1 = ph[1], l0 = pl[0], l1 = pl[1];
    int off = row * TROW + kh * 2;
    *(uint4*)(sBhi + off)      = h0;
    *(uint4*)(sBhi + off + 16) = h1;
    *(uint4*)(sBlo + off)      = l0;
    *(uint4*)(sBlo + off + 16) = l1;
}

// one K=32 chunk of warp-level MMAs (3-pass hi/lo)
__device__ __forceinline__ void compute_chunk(uint32_t Ahi, uint32_t Alo,
                                              uint32_t Bhi, uint32_t Blo,
                                              int wm, int wn, int lane,
                                              float (*acc)[4]) {
    const int aRow = lane & 15;
    const int aK8 = (lane & 16) ? 16 : 0;                 // bytes
    const int bRow = (lane & 7) + ((lane & 16) ? 8 : 0);
    const int bK8 = (lane & 8) ? 16 : 0;
#pragma unroll
    for (int ks = 0; ks < 2; ks++) {
        int kb = ks * 32;                                  // bytes within row
        uint32_t a0h[4], a1h[4], a0l[4], a1l[4];
        uint32_t ao0 = (wm * 32 + aRow) * TROW + kb + aK8;
        uint32_t ao1 = (wm * 32 + 16 + aRow) * TROW + kb + aK8;
        ldmx4(a0h, Ahi + ao0);
        ldmx4(a1h, Ahi + ao1);
        ldmx4(a0l, Alo + ao0);
        ldmx4(a1l, Alo + ao1);
#pragma unroll
        for (int ng = 0; ng < 4; ng++) {
            uint32_t bh[4], bl[4];
            uint32_t bo = (wn * 64 + ng * 16 + bRow) * TROW + kb + bK8;
            ldmx4(bh, Bhi + bo);
            ldmx4(bl, Blo + bo);
#pragma unroll
            for (int half = 0; half < 2; half++) {
                float* d0 = acc[0 + ng * 2 + half];
                float* d1 = acc[8 + ng * 2 + half];
                uint32_t b0 = bh[half * 2], b1 = bh[half * 2 + 1];
                uint32_t l0 = bl[half * 2], l1 = bl[half * 2 + 1];
                mma_bf16(d0, a0h, b0, b1);
                mma_bf16(d0, a0h, l0, l1);
                mma_bf16(d0, a0l, b0, b1);
                mma_bf16(d1, a1h, b0, b1);
                mma_bf16(d1, a1h, l0, l1);
                mma_bf16(d1, a1l, b0, b1);
            }
        }
    }
}

// ---------------------------------------------------------------------------
__global__ void zero_kernel(int n) {
    size_t i = (size_t)blockIdx.x * blockDim.x + threadIdx.x;
    size_t stride = (size_t)gridDim.x * blockDim.x;
    size_t n4 = (size_t)n * (DIM / 4);
    float4 z = make_float4(0.f, 0.f, 0.f, 0.f);
    for (size_t k = i; k < n4; k += stride) {
        ((float4*)d_agg[0])[k] = z;
        ((float4*)d_agg[1])[k] = z;
        ((float4*)d_agg[2])[k] = z;
        ((float4*)d_aggc)[k]   = z;
    }
    for (size_t k = i; k < (size_t)n; k += stride) {
        d_cnt[0][k] = 0; d_cnt[1][k] = 0; d_cnt[2][k] = 0;
    }
    if (i < DIM) { d_colsum[i] = 0.f; d_colsumsq[i] = 0.f; }
}

// ---------------------------------------------------------------------------
__global__ void prep1b_kernel(const float* __restrict__ Wl0, const float* __restrict__ Wl1,
                              const float* __restrict__ Wl2, const float* __restrict__ Wla,
                              const float* __restrict__ Wr0, const float* __restrict__ Wr1,
                              const float* __restrict__ Wr2, const float* __restrict__ Wra,
                              const float* __restrict__ bl0, const float* __restrict__ bl1,
                              const float* __restrict__ bl2, const float* __restrict__ bla,
                              const float* __restrict__ wt) {
    float w0 = wt[0], w1 = wt[1], w2 = wt[2];
    int j = blockIdx.x;
    if (j < 128) {
        for (int k = threadIdx.x; k < 640; k += blockDim.x) {
            int reg = k >> 7, km = k & 127;
            int wij = j * 128 + km;
            float v;
            switch (reg) {
                case 0:  v = w0 * Wl0[wij]; break;
                case 1:  v = w1 * Wl1[wij]; break;
                case 2:  v = w2 * Wl2[wij]; break;
                case 3:  v = Wla[wij]; break;
                default: v = w0 * Wr0[wij] + w1 * Wr1[wij] + w2 * Wr2[wij] + Wra[wij];
            }
            __nv_bfloat16 h = __float2bfloat16(v);
            d_B1hi[j * 640 + k] = h;
            d_B1lo[j * 640 + k] = __float2bfloat16(v - __bfloat162float(h));
        }
    } else if (threadIdx.x < 128) {
        int jj = threadIdx.x;
        d_bcomb[jj] = w0 * bl0[jj] + w1 * bl1[jj] + w2 * bl2[jj] + bla[jj];
    }
}

// ---------------------------------------------------------------------------
__global__ void scatter_feat_all(const float* __restrict__ feat,
                                 const int* __restrict__ e0, const int* __restrict__ e1,
                                 const int* __restrict__ e2, int E0, int E1, int E2) {
    int gw = (blockIdx.x * blockDim.x + threadIdx.x) >> 5;
    int lane = threadIdx.x & 31;
    const int* e; int t, E, idx = gw;
    if (idx < E0)              { e = e0; t = 0; E = E0; }
    else if ((idx -= E0) < E1) { e = e1; t = 1; E = E1; }
    else if ((idx -= E1) < E2) { e = e2; t = 2; E = E2; }
    else return;
    int s = __ldg(e + idx);
    int d = __ldg(e + E + idx);
    float4 v = *(const float4*)(feat + (size_t)s * DIM + lane * 4);
    red_add_v4(&d_agg[t][(size_t)d * DIM + lane * 4], v);
    if (lane == 0) atomicAdd(&d_cnt[t][d], 1);
}

__global__ void scatter_comb_all(const int* __restrict__ e0, const int* __restrict__ e1,
                                 const int* __restrict__ e2, int E0, int E1, int E2) {
    int gw = (blockIdx.x * blockDim.x + threadIdx.x) >> 5;
    int lane = threadIdx.x & 31;
    const int* e; int E, idx = gw;
    if (idx < E0)              { e = e0; E = E0; }
    else if ((idx -= E0) < E1) { e = e1; E = E1; }
    else if ((idx -= E1) < E2) { e = e2; E = E2; }
    else return;
    int s = __ldg(e + idx);
    int d = __ldg(e + E + idx);
    float4 v = *(const float4*)(d_comb + (size_t)s * DIM + lane * 4);
    red_add_v4(&d_aggc[(size_t)d * DIM + lane * 4], v);
}

// ---------------------------------------------------------------------------
__global__ void build_r_kernel(int n) {
    int i = blockIdx.x * blockDim.x + threadIdx.x;
    if (i >= n) return;
    int c0 = d_cnt[0][i], c1 = d_cnt[1][i], c2 = d_cnt[2][i];
    d_r[0][i] = 1.f / (float)(c0 > 1 ? c0 : 1);
    d_r[1][i] = 1.f / (float)(c1 > 1 ? c1 : 1);
    d_r[2][i] = 1.f / (float)(c2 > 1 ? c2 : 1);
    int ca = c0 + c1 + c2;
    d_has[i] = (ca > 0) ? 1.f : 0.f;
    d_r[3][i] = 1.f / (float)(ca > 1 ? ca : 1);
}

// ---------------------------------------------------------------------------
// GEMM1: comb = relu(X @ Wbig + bcomb), X composed on the fly.
// Pad rows read zero-initialized globals (never written) -> zero contribution.
// ---------------------------------------------------------------------------
__global__ void __launch_bounds__(256, 2)
gemm1_mma(const float* __restrict__ feat, int nrows) {
    __shared__ __align__(16) char sAhi[128 * TROW];
    __shared__ __align__(16) char sAlo[128 * TROW];
    __shared__ __align__(16) char sBhi[128 * TROW];
    __shared__ __align__(16) char sBlo[128 * TROW];

    const int tid = threadIdx.x;
    const int lane = tid & 31;
    const int wid = tid >> 5;
    const int wm = wid >> 1, wn = wid & 1;
    const int m0 = blockIdx.x * 128;
    const int arow = tid >> 1;
    const int kh = (tid & 1) * 16;
    const int r = m0 + arow;
    const size_t rowoff = (size_t)r * 128;

    const uint32_t Ahi = smem_u32(sAhi), Alo = smem_u32(sAlo);
    const uint32_t Bhi = smem_u32(sBhi), Blo = smem_u32(sBlo);

    float acc[16][4];
#pragma unroll
    for (int i = 0; i < 16; i++)
#pragma unroll
        for (int j = 0; j < 4; j++) acc[i][j] = 0.f;

    for (int ch = 0; ch < 20; ch++) {
        int c0 = ch * 32;
        int reg = c0 >> 7;
        int lk = (c0 & 127) + kh;
        float4 f0, f1, f2, f3;
        if (reg < 3) {
            float s = d_r[reg][r];
            const float4* p = (const float4*)(d_agg[reg] + rowoff + lk);
            f0 = p[0]; f1 = p[1]; f2 = p[2]; f3 = p[3];
            f0.x *= s; f0.y *= s; f0.z *= s; f0.w *= s;
            f1.x *= s; f1.y *= s; f1.z *= s; f1.w *= s;
            f2.x *= s; f2.y *= s; f2.z *= s; f2.w *= s;
            f3.x *= s; f3.y *= s; f3.z *= s; f3.w *= s;
        } else if (reg == 3) {
            float s = d_r[3][r];
            const float4* p0 = (const float4*)(d_agg[0] + rowoff + lk);
            const float4* p1 = (const float4*)(d_agg[1] + rowoff + lk);
            const float4* p2 = (const float4*)(d_agg[2] + rowoff + lk);
#pragma unroll
            for (int g = 0; g < 4; g++) {
                float4 a = p0[g], b = p1[g], c = p2[g];
                float4 o;
                o.x = (a.x + b.x + c.x) * s; o.y = (a.y + b.y + c.y) * s;
                o.z = (a.z + b.z + c.z) * s; o.w = (a.w + b.w + c.w) * s;
                if (g == 0) f0 = o; else if (g == 1) f1 = o;
                else if (g == 2) f2 = o; else f3 = o;
            }
        } else {
            bool ok = r < nrows;
            const float4* p = (const float4*)(feat + (ok ? rowoff : 0) + lk);
            f0 = p[0]; f1 = p[1]; f2 = p[2]; f3 = p[3];
            if (!ok) { f0 = make_float4(0, 0, 0, 0); f1 = f0; f2 = f0; f3 = f0; }
        }
        store16(sAhi + arow * TROW, sAlo + arow * TROW, kh * 2, f0, f1, f2, f3);
        fill_b(d_B1hi, d_B1lo, 640, c0, tid, sBhi, sBlo);
        __syncthreads();
        compute_chunk(Ahi, Alo, Bhi, Blo, wm, wn, lane, acc);
        __syncthreads();
    }

    // epilogue: bias + relu -> comb
    const int g = lane >> 2, tc = (lane & 3) * 2;
#pragma unroll
    for (int mt = 0; mt < 2; mt++) {
#pragma unroll
        for (int nt = 0; nt < 8; nt++) {
            float* a = acc[mt * 8 + nt];
            int col = wn * 64 + nt * 8 + tc;
            int row0 = m0 + wm * 32 + mt * 16 + g;
            float b0 = d_bcomb[col], b1 = d_bcomb[col + 1];
            if (row0 < nrows) {
                float2 v = make_float2(fmaxf(a[0] + b0, 0.f), fmaxf(a[1] + b1, 0.f));
                *(float2*)(d_comb + (size_t)row0 * 128 + col) = v;
            }
            if (row0 + 8 < nrows) {
                float2 v = make_float2(fmaxf(a[2] + b0, 0.f), fmaxf(a[3] + b1, 0.f));
                *(float2*)(d_comb + (size_t)(row0 + 8) * 128 + col) = v;
            }
        }
    }
}

// ---------------------------------------------------------------------------
// GEMM2: out = [r3*aggc | comb] @ B2 + b2 + has*cWf
// ---------------------------------------------------------------------------
__global__ void __launch_bounds__(256, 2)
gemm2_mma(float* __restrict__ C, int nrows) {
    __shared__ __align__(16) char sAhi[128 * TROW];
    __shared__ __align__(16) char sAlo[128 * TROW];
    __shared__ __align__(16) char sBhi[128 * TROW];
    __shared__ __align__(16) char sBlo[128 * TROW];

    const int tid = threadIdx.x;
    const int lane = tid & 31;
    const int wid = tid >> 5;
    const int wm = wid >> 1, wn = wid & 1;
    const int m0 = blockIdx.x * 128;
    const int arow = tid >> 1;
    const int kh = (tid & 1) * 16;
    const int r = m0 + arow;
    const size_t rowoff = (size_t)r * 128;

    const uint32_t Ahi = smem_u32(sAhi), Alo = smem_u32(sAlo);
    const uint32_t Bhi = smem_u32(sBhi), Blo = smem_u32(sBlo);

    float acc[16][4];
#pragma unroll
    for (int i = 0; i < 16; i++)
#pragma unroll
        for (int j = 0; j < 4; j++) acc[i][j] = 0.f;

    for (int ch = 0; ch < 8; ch++) {
        int c0 = ch * 32;
        int reg = c0 >> 7;
        int lk = (c0 & 127) + kh;
        float s = (reg == 0) ? d_r[3][r] : 1.f;
        const float* src = (reg == 0) ? d_aggc : d_comb;
        const float4* p = (const float4*)(src + rowoff + lk);
        float4 f0 = p[0], f1 = p[1], f2 = p[2], f3 = p[3];
        f0.x *= s; f0.y *= s; f0.z *= s; f0.w *= s;
        f1.x *= s; f1.y *= s; f1.z *= s; f1.w *= s;
        f2.x *= s; f2.y *= s; f2.z *= s; f2.w *= s;
        f3.x *= s; f3.y *= s; f3.z *= s; f3.w *= s;
        store16(sAhi + arow * TROW, sAlo + arow * TROW, kh * 2, f0, f1, f2, f3);
        fill_b(d_B2hi, d_B2lo, 256, c0, tid, sBhi, sBlo);
        __syncthreads();
        compute_chunk(Ahi, Alo, Bhi, Blo, wm, wn, lane, acc);
        __syncthreads();
    }

    const int g = lane >> 2, tc = (lane & 3) * 2;
#pragma unroll
    for (int mt = 0; mt < 2; mt++) {
#pragma unroll
        for (int nt = 0; nt < 8; nt++) {
            float* a = acc[mt * 8 + nt];
            int col = wn * 64 + nt * 8 + tc;
            int row0 = m0 + wm * 32 + mt * 16 + g;
            float b0 = d_b2[col], b1 = d_b2[col + 1];
            float w0 = d_cWf[col], w1 = d_cWf[col + 1];
            if (row0 < nrows) {
                float h = d_has[row0];
                float2 v = make_float2(a[0] + b0 + h * w0, a[1] + b1 + h * w1);
                *(float2*)(C + (size_t)row0 * 128 + col) = v;
            }
            if (row0 + 8 < nrows) {
                float h = d_has[row0 + 8];
                float2 v = make_float2(a[2] + b0 + h * w0, a[3] + b1 + h * w1);
                *(float2*)(C + (size_t)(row0 + 8) * 128 + col) = v;
            }
        }
    }
}

// ---------------------------------------------------------------------------
__global__ void bn_stats_kernel(int n) {
    int j = threadIdx.x;
    float s = 0.f, s2 = 0.f;
    for (int r = blockIdx.x; r < n; r += gridDim.x) {
        float v = d_comb[(size_t)r * DIM + j];
        s += v;
        s2 += v * v;
    }
    atomicAdd(&d_colsum[j], s);
    atomicAdd(&d_colsumsq[j], s2);
}

__global__ void bn_finalize_kernel(const float* __restrict__ gamma,
                                   const float* __restrict__ beta, int n) {
    int j = threadIdx.x;
    float invn = 1.f / (float)n;
    float mu = d_colsum[j] * invn;
    float var = d_colsumsq[j] * invn - mu * mu;
    float a = gamma[j] * rsqrtf(var + 1e-5f);
    d_bn_a[j] = a;
    d_bn_c[j] = beta[j] - mu * a;
}

__global__ void prep2b_kernel(const float* __restrict__ Wf, const float* __restrict__ Wrf,
                              const float* __restrict__ bf) {
    int j = blockIdx.x;
    if (j < 128) {
        int k = threadIdx.x;           // 0..255
        int km = k & 127;
        float w = ((k < 128) ? Wf[j * 128 + km] : Wrf[j * 128 + km]) * d_bn_a[km];
        __nv_bfloat16 h = __float2bfloat16(w);
        d_B2hi[j * 256 + k] = h;
        d_B2lo[j * 256 + k] = __float2bfloat16(w - __bfloat162float(h));
    } else if (threadIdx.x < 128) {
        int jj = threadIdx.x;
        float accf = 0.f, accr = 0.f;
        for (int k = 0; k < DIM; k++) {
            float c = d_bn_c[k];
            accf += c * Wf[jj * DIM + k];
            accr += c * Wrf[jj * DIM + k];
        }
        d_cWf[jj] = accf;
        d_b2[jj] = bf[jj] + accr;
    }
}

// ---------------------------------------------------------------------------
extern "C" void kernel_launch(void* const* d_in, const int* in_sizes, int n_in,
                              void* d_out, int out_size) {
    int feat_i = 0;
    for (int i = 1; i < n_in; i++)
        if (in_sizes[i] > in_sizes[feat_i]) feat_i = i;

    const float* Wm[10] = {0};
    const float* Bv[7]  = {0};
    const int*   Ee[3]  = {0};
    int Ecnt[3] = {0};
    const float* wt = nullptr;
    int wn = 0, bn = 0, en = 0;
    for (int i = 0; i < n_in; i++) {
        if (i == feat_i) continue;
        int s = in_sizes[i];
        if (s == 3)                wt = (const float*)d_in[i];
        else if (s == DIM)         { if (bn < 7)  Bv[bn++] = (const float*)d_in[i]; }
        else if (s == DIM * DIM)   { if (wn < 10) Wm[wn++] = (const float*)d_in[i]; }
        else                       { if (en < 3)  { Ee[en] = (const int*)d_in[i];
                                                    Ecnt[en] = s / 2; en++; } }
    }
    const float* feat = (const float*)d_in[feat_i];
    int n = in_sizes[feat_i] / DIM;

    const float *Wl0 = Wm[0], *Wr0 = Wm[1], *Wl1 = Wm[2], *Wr1 = Wm[3];
    const float *Wl2 = Wm[4], *Wr2 = Wm[5], *Wla = Wm[6], *Wra = Wm[7];
    const float *Wf  = Wm[8], *Wrf = Wm[9];
    const float *bl0 = Bv[0], *bl1 = Bv[1], *bl2 = Bv[2], *bla = Bv[3];
    const float *bf  = Bv[4], *gamma = Bv[5], *beta = Bv[6];

    float* out = (float*)d_out;
    int Etot = Ecnt[0] + Ecnt[1] + Ecnt[2];
    int nblk = (n + 127) / 128;

    zero_kernel<<<2048, 256>>>(n);
    prep1b_kernel<<<129, 256>>>(Wl0, Wl1, Wl2, Wla, Wr0, Wr1, Wr2, Wra,
                                bl0, bl1, bl2, bla, wt);

    scatter_feat_all<<<(Etot + 7) / 8, 256>>>(feat, Ee[0], Ee[1], Ee[2],
                                              Ecnt[0], Ecnt[1], Ecnt[2]);
    build_r_kernel<<<(n + 255) / 256, 256>>>(n);

    gemm1_mma<<<nblk, 256>>>(feat, n);

    bn_stats_kernel<<<1024, 128>>>(n);
    scatter_comb_all<<<(Etot + 7) / 8, 256>>>(Ee[0], Ee[1], Ee[2],
                                              Ecnt[0], Ecnt[1], Ecnt[2]);
    bn_finalize_kernel<<<1, 128>>>(gamma, beta, n);
    prep2b_kernel<<<129, 256>>>(Wf, Wrf, bf);

    gemm2_mma<<<nblk, 256>>>(out, n);

    (void)out_size;
}

// round 11
// speedup vs baseline: 1.7437x; 1.0665x over previous
#include <cuda_runtime.h>
#include <cuda_bf16.h>
#include <cstdint>
#include <cstdio>

// ---------------------------------------------------------------------------
// MultiSAGE fused pipeline, v8 = v6 (passing, 629us) + 4-edge/warp scatter.
// GEMMs byte-identical to v6 (unpipelined) to bisect the v7 container failure.
// ---------------------------------------------------------------------------

#define DIM 128
constexpr int MAXN = 100000;
constexpr int PADN = MAXN + 128;

__device__ __align__(16) float d_agg[3][(size_t)PADN * DIM];
__device__ int   d_cnt[3][PADN];
__device__ float d_has[PADN];
__device__ float d_r[4][PADN];
__device__ __align__(16) float d_comb[(size_t)PADN * DIM];
__device__ __align__(16) float d_aggc[(size_t)PADN * DIM];
__device__ __align__(16) __nv_bfloat16 d_B1hi[128 * 640];
__device__ __align__(16) __nv_bfloat16 d_B1lo[128 * 640];
__device__ __align__(16) __nv_bfloat16 d_B2hi[128 * 256];
__device__ __align__(16) __nv_bfloat16 d_B2lo[128 * 256];
__device__ float d_bcomb[DIM];
__device__ float d_b2[DIM];
__device__ float d_cWf[DIM];
__device__ float d_colsum[DIM];
__device__ float d_colsumsq[DIM];
__device__ __align__(16) float d_bn_a[DIM];
__device__ __align__(16) float d_bn_c[DIM];

// ---------------------------------------------------------------------------
__device__ __forceinline__ uint32_t smem_u32(const void* p) {
    uint32_t a;
    asm("{ .reg .u64 t; cvta.to.shared.u64 t, %1; cvt.u32.u64 %0, t; }"
        : "=r"(a) : "l"(p));
    return a;
}
__device__ __forceinline__ void red_add_v4(float* p, float4 v) {
    asm volatile("red.global.add.v4.f32 [%0], {%1, %2, %3, %4};"
                 :: "l"(p), "f"(v.x), "f"(v.y), "f"(v.z), "f"(v.w) : "memory");
}
__device__ __forceinline__ void ldmx4(uint32_t* r, uint32_t addr) {
    asm volatile("ldmatrix.sync.aligned.m8n8.x4.shared.b16 {%0,%1,%2,%3}, [%4];"
                 : "=r"(r[0]), "=r"(r[1]), "=r"(r[2]), "=r"(r[3]) : "r"(addr));
}
__device__ __forceinline__ void mma_bf16(float* d, const uint32_t* a,
                                         uint32_t b0, uint32_t b1) {
    asm volatile(
        "mma.sync.aligned.m16n8k16.row.col.f32.bf16.bf16.f32 "
        "{%0,%1,%2,%3}, {%4,%5,%6,%7}, {%8,%9}, {%0,%1,%2,%3};"
        : "+f"(d[0]), "+f"(d[1]), "+f"(d[2]), "+f"(d[3])
        : "r"(a[0]), "r"(a[1]), "r"(a[2]), "r"(a[3]), "r"(b0), "r"(b1));
}
__device__ __forceinline__ uint32_t pack_bf2(float a, float b) {
    __nv_bfloat162 t;
    t.x = __float2bfloat16(a);
    t.y = __float2bfloat16(b);
    return *reinterpret_cast<uint32_t*>(&t);
}
__device__ __forceinline__ float bf_round(float a) {
    return __bfloat162float(__float2bfloat16(a));
}

constexpr int TROW = 80;

__device__ __forceinline__ void store16(char* hi, char* lo, int off,
                                        float4 f0, float4 f1, float4 f2, float4 f3) {
    uint4 H0, H1, L0, L1;
    H0.x = pack_bf2(f0.x, f0.y); H0.y = pack_bf2(f0.z, f0.w);
    H0.z = pack_bf2(f1.x, f1.y); H0.w = pack_bf2(f1.z, f1.w);
    H1.x = pack_bf2(f2.x, f2.y); H1.y = pack_bf2(f2.z, f2.w);
    H1.z = pack_bf2(f3.x, f3.y); H1.w = pack_bf2(f3.z, f3.w);
    L0.x = pack_bf2(f0.x - bf_round(f0.x), f0.y - bf_round(f0.y));
    L0.y = pack_bf2(f0.z - bf_round(f0.z), f0.w - bf_round(f0.w));
    L0.z = pack_bf2(f1.x - bf_round(f1.x), f1.y - bf_round(f1.y));
    L0.w = pack_bf2(f1.z - bf_round(f1.z), f1.w - bf_round(f1.w));
    L1.x = pack_bf2(f2.x - bf_round(f2.x), f2.y - bf_round(f2.y));
    L1.y = pack_bf2(f2.z - bf_round(f2.z), f2.w - bf_round(f2.w));
    L1.z = pack_bf2(f3.x - bf_round(f3.x), f3.y - bf_round(f3.y));
    L1.w = pack_bf2(f3.z - bf_round(f3.z), f3.w - bf_round(f3.w));
    *(uint4*)(hi + off)      = H0;
    *(uint4*)(hi + off + 16) = H1;
    *(uint4*)(lo + off)      = L0;
    *(uint4*)(lo + off + 16) = L1;
}

__device__ __forceinline__ void fill_b(const __nv_bfloat16* __restrict__ Bh,
                                       const __nv_bfloat16* __restrict__ Bl,
                                       int Ktot, int c0, int tid,
                                       char* sBhi, char* sBlo) {
    int row = tid >> 1, kh = (tid & 1) * 16;
    const uint4* ph = (const uint4*)(Bh + (size_t)row * Ktot + c0 + kh);
    const uint4* pl = (const uint4*)(Bl + (size_t)row * Ktot + c0 + kh);
    uint4 h0 = ph[0], h1 = ph[1], l0 = pl[0], l1 = pl[1];
    int off = row * TROW + kh * 2;
    *(uint4*)(sBhi + off)      = h0;
    *(uint4*)(sBhi + off + 16) = h1;
    *(uint4*)(sBlo + off)      = l0;
    *(uint4*)(sBlo + off + 16) = l1;
}

__device__ __forceinline__ void compute_chunk(uint32_t Ahi, uint32_t Alo,
                                              uint32_t Bhi, uint32_t Blo,
                                              int wm, int wn, int lane,
                                              float (*acc)[4]) {
    const int aRow = lane & 15;
    const int aK8 = (lane & 16) ? 16 : 0;
    const int bRow = (lane & 7) + ((lane & 16) ? 8 : 0);
    const int bK8 = (lane & 8) ? 16 : 0;
#pragma unroll
    for (int ks = 0; ks < 2; ks++) {
        int kb = ks * 32;
        uint32_t a0h[4], a1h[4], a0l[4], a1l[4];
        uint32_t ao0 = (wm * 32 + aRow) * TROW + kb + aK8;
        uint32_t ao1 = (wm * 32 + 16 + aRow) * TROW + kb + aK8;
        ldmx4(a0h, Ahi + ao0);
        ldmx4(a1h, Ahi + ao1);
        ldmx4(a0l, Alo + ao0);
        ldmx4(a1l, Alo + ao1);
#pragma unroll
        for (int ng = 0; ng < 4; ng++) {
            uint32_t bh[4], bl[4];
            uint32_t bo = (wn * 64 + ng * 16 + bRow) * TROW + kb + bK8;
            ldmx4(bh, Bhi + bo);
            ldmx4(bl, Blo + bo);
#pragma unroll
            for (int half = 0; half < 2; half++) {
                float* d0 = acc[0 + ng * 2 + half];
                float* d1 = acc[8 + ng * 2 + half];
                uint32_t b0 = bh[half * 2], b1 = bh[half * 2 + 1];
                uint32_t l0 = bl[half * 2], l1 = bl[half * 2 + 1];
                mma_bf16(d0, a0h, b0, b1);
                mma_bf16(d0, a0h, l0, l1);
                mma_bf16(d0, a0l, b0, b1);
                mma_bf16(d1, a1h, b0, b1);
                mma_bf16(d1, a1h, l0, l1);
                mma_bf16(d1, a1l, b0, b1);
            }
        }
    }
}

// ---------------------------------------------------------------------------
__global__ void zero_kernel(int n) {
    size_t i = (size_t)blockIdx.x * blockDim.x + threadIdx.x;
    size_t stride = (size_t)gridDim.x * blockDim.x;
    size_t n4 = (size_t)n * (DIM / 4);
    float4 z = make_float4(0.f, 0.f, 0.f, 0.f);
    for (size_t k = i; k < n4; k += stride) {
        ((float4*)d_agg[0])[k] = z;
        ((float4*)d_agg[1])[k] = z;
        ((float4*)d_agg[2])[k] = z;
        ((float4*)d_aggc)[k]   = z;
    }
    for (size_t k = i; k < (size_t)n; k += stride) {
        d_cnt[0][k] = 0; d_cnt[1][k] = 0; d_cnt[2][k] = 0;
    }
    if (i < DIM) { d_colsum[i] = 0.f; d_colsumsq[i] = 0.f; }
}

// ---------------------------------------------------------------------------
__global__ void prep1b_kernel(const float* __restrict__ Wl0, const float* __restrict__ Wl1,
                              const float* __restrict__ Wl2, const float* __restrict__ Wla,
                              const float* __restrict__ Wr0, const float* __restrict__ Wr1,
                              const float* __restrict__ Wr2, const float* __restrict__ Wra,
                              const float* __restrict__ bl0, const float* __restrict__ bl1,
                              const float* __restrict__ bl2, const float* __restrict__ bla,
                              const float* __restrict__ wt) {
    float w0 = wt[0], w1 = wt[1], w2 = wt[2];
    int j = blockIdx.x;
    if (j < 128) {
        for (int k = threadIdx.x; k < 640; k += blockDim.x) {
            int reg = k >> 7, km = k & 127;
            int wij = j * 128 + km;
            float v;
            switch (reg) {
                case 0:  v = w0 * Wl0[wij]; break;
                case 1:  v = w1 * Wl1[wij]; break;
                case 2:  v = w2 * Wl2[wij]; break;
                case 3:  v = Wla[wij]; break;
                default: v = w0 * Wr0[wij] + w1 * Wr1[wij] + w2 * Wr2[wij] + Wra[wij];
            }
            __nv_bfloat16 h = __float2bfloat16(v);
            d_B1hi[j * 640 + k] = h;
            d_B1lo[j * 640 + k] = __float2bfloat16(v - __bfloat162float(h));
        }
    } else if (threadIdx.x < 128) {
        int jj = threadIdx.x;
        d_bcomb[jj] = w0 * bl0[jj] + w1 * bl1[jj] + w2 * bl2[jj] + bla[jj];
    }
}

// ---------------------------------------------------------------------------
// scatter, 4 edges per warp (independent gathers -> MLP 4)
// ---------------------------------------------------------------------------
__global__ void scatter_feat_all(const float* __restrict__ feat,
                                 const int* __restrict__ e0, const int* __restrict__ e1,
                                 const int* __restrict__ e2, int E0, int E1, int E2) {
    int gw = (blockIdx.x * blockDim.x + threadIdx.x) >> 5;
    int lane = threadIdx.x & 31;
    int base = gw * 4;
    int Etot = E0 + E1 + E2;

    int s[4], d[4], t[4];
    bool ok[4];
#pragma unroll
    for (int j = 0; j < 4; j++) {
        int idx = base + j;
        ok[j] = idx < Etot;
        s[j] = 0; d[j] = 0; t[j] = 0;
        if (ok[j]) {
            const int* e; int E, tt;
            if (idx < E0)              { e = e0; E = E0; tt = 0; }
            else if ((idx -= E0) < E1) { e = e1; E = E1; tt = 1; }
            else                       { idx -= E1; e = e2; E = E2; tt = 2; }
            s[j] = __ldg(e + idx);
            d[j] = __ldg(e + E + idx);
            t[j] = tt;
        }
    }
    float4 v[4];
#pragma unroll
    for (int j = 0; j < 4; j++)
        if (ok[j]) v[j] = *(const float4*)(feat + (size_t)s[j] * DIM + lane * 4);
#pragma unroll
    for (int j = 0; j < 4; j++) {
        if (ok[j]) {
            red_add_v4(&d_agg[t[j]][(size_t)d[j] * DIM + lane * 4], v[j]);
            if (lane == 0) atomicAdd(&d_cnt[t[j]][d[j]], 1);
        }
    }
}

__global__ void scatter_comb_all(const int* __restrict__ e0, const int* __restrict__ e1,
                                 const int* __restrict__ e2, int E0, int E1, int E2) {
    int gw = (blockIdx.x * blockDim.x + threadIdx.x) >> 5;
    int lane = threadIdx.x & 31;
    int base = gw * 4;
    int Etot = E0 + E1 + E2;

    int s[4], d[4];
    bool ok[4];
#pragma unroll
    for (int j = 0; j < 4; j++) {
        int idx = base + j;
        ok[j] = idx < Etot;
        s[j] = 0; d[j] = 0;
        if (ok[j]) {
            const int* e; int E;
            if (idx < E0)              { e = e0; E = E0; }
            else if ((idx -= E0) < E1) { e = e1; E = E1; }
            else                       { idx -= E1; e = e2; E = E2; }
            s[j] = __ldg(e + idx);
            d[j] = __ldg(e + E + idx);
        }
    }
    float4 v[4];
#pragma unroll
    for (int j = 0; j < 4; j++)
        if (ok[j]) v[j] = *(const float4*)(d_comb + (size_t)s[j] * DIM + lane * 4);
#pragma unroll
    for (int j = 0; j < 4; j++)
        if (ok[j]) red_add_v4(&d_aggc[(size_t)d[j] * DIM + lane * 4], v[j]);
}

// ---------------------------------------------------------------------------
__global__ void build_r_kernel(int n) {
    int i = blockIdx.x * blockDim.x + threadIdx.x;
    if (i >= n) return;
    int c0 = d_cnt[0][i], c1 = d_cnt[1][i], c2 = d_cnt[2][i];
    d_r[0][i] = 1.f / (float)(c0 > 1 ? c0 : 1);
    d_r[1][i] = 1.f / (float)(c1 > 1 ? c1 : 1);
    d_r[2][i] = 1.f / (float)(c2 > 1 ? c2 : 1);
    int ca = c0 + c1 + c2;
    d_has[i] = (ca > 0) ? 1.f : 0.f;
    d_r[3][i] = 1.f / (float)(ca > 1 ? ca : 1);
}

// ---------------------------------------------------------------------------
// GEMM1: comb = relu(X @ Wbig + bcomb), X composed on the fly (v6-identical)
// ---------------------------------------------------------------------------
__global__ void __launch_bounds__(256, 2)
gemm1_mma(const float* __restrict__ feat, int nrows) {
    __shared__ __align__(16) char sAhi[128 * TROW];
    __shared__ __align__(16) char sAlo[128 * TROW];
    __shared__ __align__(16) char sBhi[128 * TROW];
    __shared__ __align__(16) char sBlo[128 * TROW];

    const int tid = threadIdx.x;
    const int lane = tid & 31;
    const int wid = tid >> 5;
    const int wm = wid >> 1, wn = wid & 1;
    const int m0 = blockIdx.x * 128;
    const int arow = tid >> 1;
    const int kh = (tid & 1) * 16;
    const int r = m0 + arow;
    const size_t rowoff = (size_t)r * 128;

    const uint32_t Ahi = smem_u32(sAhi), Alo = smem_u32(sAlo);
    const uint32_t Bhi = smem_u32(sBhi), Blo = smem_u32(sBlo);

    float acc[16][4];
#pragma unroll
    for (int i = 0; i < 16; i++)
#pragma unroll
        for (int j = 0; j < 4; j++) acc[i][j] = 0.f;

    for (int ch = 0; ch < 20; ch++) {
        int c0 = ch * 32;
        int reg = c0 >> 7;
        int lk = (c0 & 127) + kh;
        float4 f0, f1, f2, f3;
        if (reg < 3) {
            float s = d_r[reg][r];
            const float4* p = (const float4*)(d_agg[reg] + rowoff + lk);
            f0 = p[0]; f1 = p[1]; f2 = p[2]; f3 = p[3];
            f0.x *= s; f0.y *= s; f0.z *= s; f0.w *= s;
            f1.x *= s; f1.y *= s; f1.z *= s; f1.w *= s;
            f2.x *= s; f2.y *= s; f2.z *= s; f2.w *= s;
            f3.x *= s; f3.y *= s; f3.z *= s; f3.w *= s;
        } else if (reg == 3) {
            float s = d_r[3][r];
            const float4* p0 = (const float4*)(d_agg[0] + rowoff + lk);
            const float4* p1 = (const float4*)(d_agg[1] + rowoff + lk);
            const float4* p2 = (const float4*)(d_agg[2] + rowoff + lk);
#pragma unroll
            for (int g = 0; g < 4; g++) {
                float4 a = p0[g], b = p1[g], c = p2[g];
                float4 o;
                o.x = (a.x + b.x + c.x) * s; o.y = (a.y + b.y + c.y) * s;
                o.z = (a.z + b.z + c.z) * s; o.w = (a.w + b.w + c.w) * s;
                if (g == 0) f0 = o; else if (g == 1) f1 = o;
                else if (g == 2) f2 = o; else f3 = o;
            }
        } else {
            bool ok = r < nrows;
            const float4* p = (const float4*)(feat + (ok ? rowoff : 0) + lk);
            f0 = p[0]; f1 = p[1]; f2 = p[2]; f3 = p[3];
            if (!ok) { f0 = make_float4(0, 0, 0, 0); f1 = f0; f2 = f0; f3 = f0; }
        }
        store16(sAhi + arow * TROW, sAlo + arow * TROW, kh * 2, f0, f1, f2, f3);
        fill_b(d_B1hi, d_B1lo, 640, c0, tid, sBhi, sBlo);
        __syncthreads();
        compute_chunk(Ahi, Alo, Bhi, Blo, wm, wn, lane, acc);
        __syncthreads();
    }

    const int g = lane >> 2, tc = (lane & 3) * 2;
#pragma unroll
    for (int mt = 0; mt < 2; mt++) {
#pragma unroll
        for (int nt = 0; nt < 8; nt++) {
            float* a = acc[mt * 8 + nt];
            int col = wn * 64 + nt * 8 + tc;
            int row0 = m0 + wm * 32 + mt * 16 + g;
            float b0 = d_bcomb[col], b1 = d_bcomb[col + 1];
            if (row0 < nrows) {
                float2 v = make_float2(fmaxf(a[0] + b0, 0.f), fmaxf(a[1] + b1, 0.f));
                *(float2*)(d_comb + (size_t)row0 * 128 + col) = v;
            }
            if (row0 + 8 < nrows) {
                float2 v = make_float2(fmaxf(a[2] + b0, 0.f), fmaxf(a[3] + b1, 0.f));
                *(float2*)(d_comb + (size_t)(row0 + 8) * 128 + col) = v;
            }
        }
    }
}

// ---------------------------------------------------------------------------
// GEMM2: out = [r3*aggc | comb] @ B2 + b2 + has*cWf (v6-identical)
// ---------------------------------------------------------------------------
__global__ void __launch_bounds__(256, 2)
gemm2_mma(float* __restrict__ C, int nrows) {
    __shared__ __align__(16) char sAhi[128 * TROW];
    __shared__ __align__(16) char sAlo[128 * TROW];
    __shared__ __align__(16) char sBhi[128 * TROW];
    __shared__ __align__(16) char sBlo[128 * TROW];

    const int tid = threadIdx.x;
    const int lane = tid & 31;
    const int wid = tid >> 5;
    const int wm = wid >> 1, wn = wid & 1;
    const int m0 = blockIdx.x * 128;
    const int arow = tid >> 1;
    const int kh = (tid & 1) * 16;
    const int r = m0 + arow;
    const size_t rowoff = (size_t)r * 128;

    const uint32_t Ahi = smem_u32(sAhi), Alo = smem_u32(sAlo);
    const uint32_t Bhi = smem_u32(sBhi), Blo = smem_u32(sBlo);

    float acc[16][4];
#pragma unroll
    for (int i = 0; i < 16; i++)
#pragma unroll
        for (int j = 0; j < 4; j++) acc[i][j] = 0.f;

    for (int ch = 0; ch < 8; ch++) {
        int c0 = ch * 32;
        int reg = c0 >> 7;
        int lk = (c0 & 127) + kh;
        float s = (reg == 0) ? d_r[3][r] : 1.f;
        const float* src = (reg == 0) ? d_aggc : d_comb;
        const float4* p = (const float4*)(src + rowoff + lk);
        float4 f0 = p[0], f1 = p[1], f2 = p[2], f3 = p[3];
        f0.x *= s; f0.y *= s; f0.z *= s; f0.w *= s;
        f1.x *= s; f1.y *= s; f1.z *= s; f1.w *= s;
        f2.x *= s; f2.y *= s; f2.z *= s; f2.w *= s;
        f3.x *= s; f3.y *= s; f3.z *= s; f3.w *= s;
        store16(sAhi + arow * TROW, sAlo + arow * TROW, kh * 2, f0, f1, f2, f3);
        fill_b(d_B2hi, d_B2lo, 256, c0, tid, sBhi, sBlo);
        __syncthreads();
        compute_chunk(Ahi, Alo, Bhi, Blo, wm, wn, lane, acc);
        __syncthreads();
    }

    const int g = lane >> 2, tc = (lane & 3) * 2;
#pragma unroll
    for (int mt = 0; mt < 2; mt++) {
#pragma unroll
        for (int nt = 0; nt < 8; nt++) {
            float* a = acc[mt * 8 + nt];
            int col = wn * 64 + nt * 8 + tc;
            int row0 = m0 + wm * 32 + mt * 16 + g;
            float b0 = d_b2[col], b1 = d_b2[col + 1];
            float w0 = d_cWf[col], w1 = d_cWf[col + 1];
            if (row0 < nrows) {
                float h = d_has[row0];
                float2 v = make_float2(a[0] + b0 + h * w0, a[1] + b1 + h * w1);
                *(float2*)(C + (size_t)row0 * 128 + col) = v;
            }
            if (row0 + 8 < nrows) {
                float h = d_has[row0 + 8];
                float2 v = make_float2(a[2] + b0 + h * w0, a[3] + b1 + h * w1);
                *(float2*)(C + (size_t)(row0 + 8) * 128 + col) = v;
            }
        }
    }
}

// ---------------------------------------------------------------------------
__global__ void bn_stats_kernel(int n) {
    int j = threadIdx.x;
    float s = 0.f, s2 = 0.f;
    for (int r = blockIdx.x; r < n; r += gridDim.x) {
        float v = d_comb[(size_t)r * DIM + j];
        s += v;
        s2 += v * v;
    }
    atomicAdd(&d_colsum[j], s);
    atomicAdd(&d_colsumsq[j], s2);
}

__global__ void bn_finalize_kernel(const float* __restrict__ gamma,
                                   const float* __restrict__ beta, int n) {
    int j = threadIdx.x;
    float invn = 1.f / (float)n;
    float mu = d_colsum[j] * invn;
    float var = d_colsumsq[j] * invn - mu * mu;
    float a = gamma[j] * rsqrtf(var + 1e-5f);
    d_bn_a[j] = a;
    d_bn_c[j] = beta[j] - mu * a;
}

__global__ void prep2b_kernel(const float* __restrict__ Wf, const float* __restrict__ Wrf,
                              const float* __restrict__ bf) {
    int j = blockIdx.x;
    if (j < 128) {
        int k = threadIdx.x;
        int km = k & 127;
        float w = ((k < 128) ? Wf[j * 128 + km] : Wrf[j * 128 + km]) * d_bn_a[km];
        __nv_bfloat16 h = __float2bfloat16(w);
        d_B2hi[j * 256 + k] = h;
        d_B2lo[j * 256 + k] = __float2bfloat16(w - __bfloat162float(h));
    } else if (threadIdx.x < 128) {
        int jj = threadIdx.x;
        float accf = 0.f, accr = 0.f;
        for (int k = 0; k < DIM; k++) {
            float c = d_bn_c[k];
            accf += c * Wf[jj * DIM + k];
            accr += c * Wrf[jj * DIM + k];
        }
        d_cWf[jj] = accf;
        d_b2[jj] = bf[jj] + accr;
    }
}

// ---------------------------------------------------------------------------
extern "C" void kernel_launch(void* const* d_in, const int* in_sizes, int n_in,
                              void* d_out, int out_size) {
    int feat_i = 0;
    for (int i = 1; i < n_in; i++)
        if (in_sizes[i] > in_sizes[feat_i]) feat_i = i;

    const float* Wm[10] = {0};
    const float* Bv[7]  = {0};
    const int*   Ee[3]  = {0};
    int Ecnt[3] = {0};
    const float* wt = nullptr;
    int wn = 0, bn = 0, en = 0;
    for (int i = 0; i < n_in; i++) {
        if (i == feat_i) continue;
        int s = in_sizes[i];
        if (s == 3)                wt = (const float*)d_in[i];
        else if (s == DIM)         { if (bn < 7)  Bv[bn++] = (const float*)d_in[i]; }
        else if (s == DIM * DIM)   { if (wn < 10) Wm[wn++] = (const float*)d_in[i]; }
        else                       { if (en < 3)  { Ee[en] = (const int*)d_in[i];
                                                    Ecnt[en] = s / 2; en++; } }
    }
    const float* feat = (const float*)d_in[feat_i];
    int n = in_sizes[feat_i] / DIM;

    const float *Wl0 = Wm[0], *Wr0 = Wm[1], *Wl1 = Wm[2], *Wr1 = Wm[3];
    const float *Wl2 = Wm[4], *Wr2 = Wm[5], *Wla = Wm[6], *Wra = Wm[7];
    const float *Wf  = Wm[8], *Wrf = Wm[9];
    const float *bl0 = Bv[0], *bl1 = Bv[1], *bl2 = Bv[2], *bla = Bv[3];
    const float *bf  = Bv[4], *gamma = Bv[5], *beta = Bv[6];

    float* out = (float*)d_out;
    int Etot = Ecnt[0] + Ecnt[1] + Ecnt[2];
    int nblk = (n + 127) / 128;
    int swarps = (Etot + 3) / 4;
    int sblk = (swarps + 7) / 8;

    zero_kernel<<<2048, 256>>>(n);
    prep1b_kernel<<<129, 256>>>(Wl0, Wl1, Wl2, Wla, Wr0, Wr1, Wr2, Wra,
                                bl0, bl1, bl2, bla, wt);

    scatter_feat_all<<<sblk, 256>>>(feat, Ee[0], Ee[1], Ee[2],
                                    Ecnt[0], Ecnt[1], Ecnt[2]);
    build_r_kernel<<<(n + 255) / 256, 256>>>(n);

    gemm1_mma<<<nblk, 256>>>(feat, n);

    bn_stats_kernel<<<1024, 128>>>(n);
    scatter_comb_all<<<sblk, 256>>>(Ee[0], Ee[1], Ee[2],
                                    Ecnt[0], Ecnt[1], Ecnt[2]);
    bn_finalize_kernel<<<1, 128>>>(gamma, beta, n);
    prep2b_kernel<<<129, 256>>>(Wf, Wrf, bf);

    gemm2_mma<<<nblk, 256>>>(out, n);

    (void)out_size;
}